// round 3
// baseline (speedup 1.0000x reference)
#include <cuda_runtime.h>
#include <cstdint>

#define NN 200000
#define EE 8192
#define HH 64
#define EAA 32
#define AA 50
#define DF 128

#define NBLK 148
#define NTHR 512
#define NWARP (NTHR / 32)
#define TOTWARP (NBLK * NWARP)

// ---- persist shared memory layout (floats) ----
#define WMT_STRIDE 196
#define OFF_WMT 0
#define SZ_WMT (64 * WMT_STRIDE)            // 12544 (W_msg transposed, padded stride)
#define OFF_WIH (OFF_WMT + SZ_WMT)          // 12544
#define OFF_WHH (OFF_WIH + 16384)           // 28928
#define OFF_BM  (OFF_WHH + 16384)           // 45312
#define OFF_BL  (OFF_BM + 64)               // 45376
#define OFF_TW  (OFF_BL + 256)              // 45632
#define OFF_TB  (OFF_TW + 32)               // 45664
#define OFF_FEAT (OFF_TB + 32)              // 45696  (NWARP * 384: two events/warp)
#define OFF_M   (OFF_FEAT + NWARP * 384)    // 51840  (NWARP * 256)
#define SMEM_FLOATS (OFF_M + NWARP * 256)   // 55936
#define SMEM_BYTES (SMEM_FLOATS * 4)        // 223744

#define PRE_SMEM_BYTES (2 * EE * 4)         // 64KB
#define SCHED_SMEM_BYTES (5 * EE * 4)       // 160KB

// ---- device scratch ----
__device__ float g_h[(size_t)NN * HH];
__device__ float g_c[(size_t)NN * HH];
__device__ int   g_done[EE];
__device__ int   g_prev_s[EE];
__device__ int   g_prev_d[EE];
__device__ int   g_pair_a[EE];
__device__ int   g_pair_b[EE];
__device__ int   g_npairs;
__device__ float g_Wc[192 * AA];
__device__ float g_bc[AA];
__device__ unsigned g_bar_cnt;
__device__ volatile unsigned g_bar_gen;

__device__ __forceinline__ void grid_bar() {
    __syncthreads();
    if (threadIdx.x == 0) {
        __threadfence();
        unsigned gen = g_bar_gen;
        if (atomicAdd(&g_bar_cnt, 1u) == (unsigned)(gridDim.x - 1u)) {
            g_bar_cnt = 0u;
            __threadfence();
            g_bar_gen = gen + 1u;
        } else {
            while (g_bar_gen == gen) __nanosleep(128);
            __threadfence();
        }
    }
    __syncthreads();
}

__device__ __forceinline__ float sigf(float v) { return 1.0f / (1.0f + __expf(-v)); }
__device__ __forceinline__ float tanhf_(float v) {
    float e = __expf(2.0f * v);
    return 1.0f - 2.0f / (e + 1.0f);
}

#define FMA4(acc, f, wv)                     \
    acc = fmaf((f).x, (wv).x, acc);          \
    acc = fmaf((f).y, (wv).y, acc);          \
    acc = fmaf((f).z, (wv).z, acc);          \
    acc = fmaf((f).w, (wv).w, acc);

#define LSTM_STEP(acc, mm, hv, wA, wB, uA, uB)        \
    acc[0] = fmaf(mm, (wA).x, acc[0]);                \
    acc[1] = fmaf(mm, (wA).y, acc[1]);                \
    acc[2] = fmaf(mm, (wA).z, acc[2]);                \
    acc[3] = fmaf(mm, (wA).w, acc[3]);                \
    acc[4] = fmaf(mm, (wB).x, acc[4]);                \
    acc[5] = fmaf(mm, (wB).y, acc[5]);                \
    acc[6] = fmaf(mm, (wB).z, acc[6]);                \
    acc[7] = fmaf(mm, (wB).w, acc[7]);                \
    acc[0] = fmaf(hv, (uA).x, acc[0]);                \
    acc[1] = fmaf(hv, (uA).y, acc[1]);                \
    acc[2] = fmaf(hv, (uA).z, acc[2]);                \
    acc[3] = fmaf(hv, (uA).w, acc[3]);                \
    acc[4] = fmaf(hv, (uB).x, acc[4]);                \
    acc[5] = fmaf(hv, (uB).y, acc[5]);                \
    acc[6] = fmaf(hv, (uB).z, acc[6]);                \
    acc[7] = fmaf(hv, (uB).w, acc[7]);

// LSTM epilogue for ONE event: acc0=row0(src), acc1=row1(dst). Writers fence.
__device__ __forceinline__ void lstm_epilogue(float* acc0, float* acc1, int src, int dst,
                                              int lane) {
    float f0g[4], o0g[4], f1g[4], o1g[4];
#pragma unroll
    for (int c2 = 0; c2 < 4; c2++) {
        f0g[c2] = __shfl_down_sync(0xffffffffu, acc0[c2], 16);
        o0g[c2] = __shfl_down_sync(0xffffffffu, acc0[4 + c2], 16);
        f1g[c2] = __shfl_down_sync(0xffffffffu, acc1[c2], 16);
        o1g[c2] = __shfl_down_sync(0xffffffffu, acc1[4 + c2], 16);
    }
    if (lane < 16) {
        float4 c0 = *(const float4*)(g_c + (size_t)src * HH + 4 * lane);
        float4 c1 = *(const float4*)(g_c + (size_t)dst * HH + 4 * lane);
        float c0a[4] = {c0.x, c0.y, c0.z, c0.w};
        float c1a[4] = {c1.x, c1.y, c1.z, c1.w};
        float cn0[4], hn0[4], cn1[4], hn1[4];
#pragma unroll
        for (int c2 = 0; c2 < 4; c2++) {
            cn0[c2] = sigf(f0g[c2]) * c0a[c2] + sigf(acc0[c2]) * tanhf_(acc0[4 + c2]);
            hn0[c2] = sigf(o0g[c2]) * tanhf_(cn0[c2]);
            cn1[c2] = sigf(f1g[c2]) * c1a[c2] + sigf(acc1[c2]) * tanhf_(acc1[4 + c2]);
            hn1[c2] = sigf(o1g[c2]) * tanhf_(cn1[c2]);
        }
        if (src != dst) {  // if src==dst the dst (row 1) update wins, matching scatter
            *(float4*)(g_h + (size_t)src * HH + 4 * lane) = make_float4(hn0[0], hn0[1], hn0[2], hn0[3]);
            *(float4*)(g_c + (size_t)src * HH + 4 * lane) = make_float4(cn0[0], cn0[1], cn0[2], cn0[3]);
        }
        *(float4*)(g_h + (size_t)dst * HH + 4 * lane) = make_float4(hn1[0], hn1[1], hn1[2], hn1[3]);
        *(float4*)(g_c + (size_t)dst * HH + 4 * lane) = make_float4(cn1[0], cn1[1], cn1[2], cn1[3]);
        __threadfence();  // each WRITER publishes its own stores to gpu scope
    }
    __syncwarp();
}

// ---- combined prepass: blocks [0,512) prev-chains; blocks [512,576) init ----
__global__ void __launch_bounds__(512, 1) k_pre(const int* __restrict__ ei,
                                                const float* __restrict__ Wemb,
                                                const float* __restrict__ bemb,
                                                const float* __restrict__ Wcls,
                                                const float* __restrict__ bcls) {
    extern __shared__ int sh[];
    const int tid = threadIdx.x;
    if (blockIdx.x < 512) {
        int* ss = sh;
        int* sd = sh + EE;
        for (int i = tid; i < EE; i += 512) {
            ss[i] = ei[i];
            sd[i] = ei[EE + i];
        }
        __syncthreads();
        int e = blockIdx.x * 16 + (tid >> 5);
        int lane = tid & 31;
        int s = ss[e], d = sd[e];
        int ps = -1, pd = -1;
        for (int j = lane; j < e; j += 32) {  // ascending j keeps the max
            int a = ss[j], b = sd[j];
            if (a == s || b == s) ps = j;
            if (a == d || b == d) pd = j;
        }
#pragma unroll
        for (int o = 16; o; o >>= 1) {
            ps = max(ps, __shfl_xor_sync(0xffffffffu, ps, o));
            pd = max(pd, __shfl_xor_sync(0xffffffffu, pd, o));
        }
        if (lane == 0) { g_prev_s[e] = ps; g_prev_d[e] = pd; }
    } else {
        float* sw = (float*)sh;  // W_cls staged [64][50]
        for (int i = tid; i < HH * AA; i += 512) sw[i] = Wcls[i];
        __syncthreads();
        int t = (blockIdx.x - 512) * 512 + tid;  // [0, 32768)
        if (t < 2 * EE) {
            int v = ei[t];
            float4 z = make_float4(0.f, 0.f, 0.f, 0.f);
            float4* hp = (float4*)(g_h + (size_t)v * HH);
            float4* cp = (float4*)(g_c + (size_t)v * HH);
#pragma unroll
            for (int i = 0; i < 16; i++) { hp[i] = z; cp[i] = z; }
        }
        if (t < EE) g_done[t] = 0;
        if (t < 192 * AA) {
            int k = t / AA, a = t - k * AA;
            float s = 0.0f;
            const float* wr = Wemb + k * HH;
#pragma unroll 8
            for (int j = 0; j < HH; j++) s = fmaf(wr[j], sw[j * AA + a], s);
            g_Wc[t] = s;
        }
        if (t < AA) {
            float s = bcls[t];
            for (int j = 0; j < HH; j++) s = fmaf(bemb[j], sw[j * AA + t], s);
            g_bc[t] = s;
        }
        if (t == 0) { g_bar_cnt = 0u; g_bar_gen = 0u; }
    }
}

// ---- scheduler: levels (exact fixpoint) -> counting sort -> same-level pairs ----
// Two events with equal level share no node and no ancestry => safe to fuse.
__global__ void __launch_bounds__(1024, 1) k_sched() {
    extern __shared__ int si[];
    int* s_lvl  = si;              // level per event
    int* s_a    = si + EE;         // counts / offsets
    int* s_b    = si + 2 * EE;     // exclusive base per level
    int* s_ps   = si + 3 * EE;     // prev_s, later sched[]
    int* s_pd   = si + 4 * EE;     // prev_d, later scan buffer / pbase
    __shared__ int s_changed, s_lmax;
    const int tid = threadIdx.x;

    for (int e = tid; e < EE; e += 1024) {
        s_ps[e] = g_prev_s[e];
        s_pd[e] = g_prev_d[e];
        s_lvl[e] = 0;
    }
    if (tid == 0) s_lmax = 0;
    __syncthreads();

    // Jacobi relaxation to exact fixpoint (monotone; terminates on clean pass)
    for (int it = 0; it < EE; ++it) {
        if (tid == 0) s_changed = 0;
        __syncthreads();
        int any = 0;
        for (int e = tid; e < EE; e += 1024) {
            int ps = s_ps[e], pd = s_pd[e];
            int nl = 0;
            if (ps >= 0) nl = s_lvl[ps] + 1;
            if (pd >= 0) { int v = s_lvl[pd] + 1; nl = max(nl, v); }
            if (nl > s_lvl[e]) { s_lvl[e] = nl; any = 1; }
        }
        if (any) s_changed = 1;
        __syncthreads();
        if (!s_changed) break;
        __syncthreads();
    }
    // counts per level + max level
    for (int e = tid; e < EE; e += 1024) s_a[e] = 0;
    __syncthreads();
    {
        int lm = 0;
        for (int e = tid; e < EE; e += 1024) {
            atomicAdd(&s_a[s_lvl[e]], 1);
            lm = max(lm, s_lvl[e]);
        }
        atomicMax(&s_lmax, lm);
    }
    __syncthreads();
    // exclusive scan of counts -> s_b (Hillis-Steele ping-pong s_a <-> s_pd)
    {
        int* cur = s_a;
        int* nxt = s_pd;
        for (int d = 1; d < EE; d <<= 1) {
            for (int i = tid; i < EE; i += 1024)
                nxt[i] = cur[i] + (i >= d ? cur[i - d] : 0);
            __syncthreads();
            int* t2 = cur; cur = nxt; nxt = t2;
        }
        for (int i = tid; i < EE; i += 1024) s_b[i] = (i > 0) ? cur[i - 1] : 0;
    }
    __syncthreads();
    // scatter by level (s_a becomes per-level filled count == cnt[l])
    for (int i = tid; i < EE; i += 1024) s_a[i] = 0;
    __syncthreads();
    for (int e = tid; e < EE; e += 1024) {
        int l = s_lvl[e];
        int p = s_b[l] + atomicAdd(&s_a[l], 1);
        s_ps[p] = e;  // s_ps reused as sched[]
    }
    __syncthreads();
    // pair bases (levels are contiguous 0..lmax); tiny sequential loop
    if (tid == 0) {
        int run = 0;
        for (int l = 0; l <= s_lmax; ++l) {
            s_pd[l] = run;                 // pbase[l]
            run += (s_a[l] + 1) >> 1;
        }
        g_npairs = run;
    }
    __syncthreads();
    // emit pairs grouped by ascending level
    for (int p = tid; p < EE; p += 1024) {
        int e = s_ps[p];
        int l = s_lvl[e];
        int local = p - s_b[l];
        if ((local & 1) == 0) {
            int pi = s_pd[l] + (local >> 1);
            g_pair_a[pi] = e;
            g_pair_b[pi] = (local + 1 < s_a[l]) ? s_ps[p + 1] : -1;
        }
    }
}

// ---- persistent: dataflow over PAIRS of same-level (independent) events ----
__global__ void __launch_bounds__(NTHR, 1) k_persist(
    const float* __restrict__ x, const int* __restrict__ ei, const float* __restrict__ eattr,
    const float* __restrict__ etime, const float* __restrict__ tw, const float* __restrict__ tb,
    const float* __restrict__ Wmsg, const float* __restrict__ bmsg,
    const float* __restrict__ Wih, const float* __restrict__ Whh,
    const float* __restrict__ blstm, float* __restrict__ out) {
    extern __shared__ float sm[];
    const int tid = threadIdx.x;
    const int lane = tid & 31;
    const int wid = tid >> 5;

    for (int i = tid; i < 192 * 64; i += NTHR) {
        int k = i >> 6, j = i & 63;
        sm[OFF_WMT + j * WMT_STRIDE + k] = Wmsg[i];
    }
    {
        float4* d1 = (float4*)(sm + OFF_WIH);
        float4* d2 = (float4*)(sm + OFF_WHH);
        const float4* s1 = (const float4*)Wih;
        const float4* s2 = (const float4*)Whh;
        for (int i = tid; i < 4096; i += NTHR) { d1[i] = s1[i]; d2[i] = s2[i]; }
    }
    for (int i = tid; i < 64; i += NTHR) sm[OFF_BM + i] = bmsg[i];
    for (int i = tid; i < 256; i += NTHR) sm[OFF_BL + i] = blstm[i];
    if (tid < 32) { sm[OFF_TW + tid] = tw[tid]; sm[OFF_TB + tid] = tb[tid]; }
    __syncthreads();

    const int gw = blockIdx.x * NWARP + wid;
    float* sFA = sm + OFF_FEAT + wid * 384;
    float* sFB = sFA + 192;
    float* sMw = sm + OFF_M + wid * 256;   // [A0|A1|B0|B1] x 64
    volatile int* vdone = (volatile int*)g_done;
    const int npairs = g_npairs;

    for (int pi = gw; pi < npairs; pi += TOTWARP) {
        int eA = g_pair_a[pi];
        int eB0 = g_pair_b[pi];
        int eB = (eB0 >= 0) ? eB0 : eA;      // singleton: duplicate (idempotent)
        int sA = ei[eA], dA = ei[EE + eA];
        int sB = ei[eB], dB = ei[EE + eB];
        int p0 = g_prev_s[eA], p1 = g_prev_d[eA];
        int p2 = g_prev_s[eB], p3 = g_prev_d[eB];
        if (lane == 0) {
            int spins = 0;
            while ((p0 >= 0 && !vdone[p0]) || (p1 >= 0 && !vdone[p1]) ||
                   (p2 >= 0 && !vdone[p2]) || (p3 >= 0 && !vdone[p3])) {
                __nanosleep(40);
                if (++spins > 20000000) break;  // fail visibly, never hang
            }
        }
        __syncwarp();
        __threadfence();  // acquire: orders after flags, drops stale L1 h/c lines

        // ---- stage features per event: [hs|hd|ea|te] ----
        {
            float tA = etime[eA], tB = etime[eB];
            float twl = sm[OFF_TW + lane], tbl = sm[OFF_TB + lane];
            sFA[lane]       = g_h[(size_t)sA * HH + lane];
            sFA[32 + lane]  = g_h[(size_t)sA * HH + 32 + lane];
            sFA[64 + lane]  = g_h[(size_t)dA * HH + lane];
            sFA[96 + lane]  = g_h[(size_t)dA * HH + 32 + lane];
            sFA[128 + lane] = eattr[(size_t)eA * EAA + lane];
            sFA[160 + lane] = cosf(fmaf(tA, twl, tbl));
            sFB[lane]       = g_h[(size_t)sB * HH + lane];
            sFB[32 + lane]  = g_h[(size_t)sB * HH + 32 + lane];
            sFB[64 + lane]  = g_h[(size_t)dB * HH + lane];
            sFB[96 + lane]  = g_h[(size_t)dB * HH + 32 + lane];
            sFB[128 + lane] = eattr[(size_t)eB * EAA + lane];
            sFB[160 + lane] = cosf(fmaf(tB, twl, tbl));
        }
        __syncwarp();

        // ---- fused message GEMV: 4 rows share each weight load ----
        {
            const float4* w0p = (const float4*)(sm + OFF_WMT + lane * WMT_STRIDE);
            const float4* w1p = (const float4*)(sm + OFF_WMT + (lane + 32) * WMT_STRIDE);
            const float4* fA = (const float4*)sFA;
            const float4* fB = (const float4*)sFB;
            float bm0 = sm[OFF_BM + lane], bm1 = sm[OFF_BM + 32 + lane];
            float a00 = bm0, a01 = bm1, a10 = bm0, a11 = bm1;
            float b00 = bm0, b01 = bm1, b10 = bm0, b11 = bm1;
#pragma unroll 2
            for (int q = 0; q < 16; q++) {  // k in [0,64): row0 -> hd, row1 -> hs
                float4 w0 = w0p[q], w1 = w1p[q];
                float4 f0A = fA[16 + q], f1A = fA[q];
                float4 f0B = fB[16 + q], f1B = fB[q];
                FMA4(a00, f0A, w0); FMA4(a01, f0A, w1);
                FMA4(a10, f1A, w0); FMA4(a11, f1A, w1);
                FMA4(b00, f0B, w0); FMA4(b01, f0B, w1);
                FMA4(b10, f1B, w0); FMA4(b11, f1B, w1);
            }
#pragma unroll 2
            for (int q = 16; q < 32; q++) {  // k in [64,128): row0 -> hs, row1 -> hd
                float4 w0 = w0p[q], w1 = w1p[q];
                float4 f0A = fA[q - 16], f1A = fA[q];
                float4 f0B = fB[q - 16], f1B = fB[q];
                FMA4(a00, f0A, w0); FMA4(a01, f0A, w1);
                FMA4(a10, f1A, w0); FMA4(a11, f1A, w1);
                FMA4(b00, f0B, w0); FMA4(b01, f0B, w1);
                FMA4(b10, f1B, w0); FMA4(b11, f1B, w1);
            }
#pragma unroll 2
            for (int q = 32; q < 48; q++) {  // k in [128,192): shared ea/te per event
                float4 w0 = w0p[q], w1 = w1p[q];
                float4 fAq = fA[q], fBq = fB[q];
                FMA4(a00, fAq, w0); FMA4(a01, fAq, w1);
                FMA4(a10, fAq, w0); FMA4(a11, fAq, w1);
                FMA4(b00, fBq, w0); FMA4(b01, fBq, w1);
                FMA4(b10, fBq, w0); FMA4(b11, fBq, w1);
            }
            sMw[lane]       = fmaxf(a00, 0.0f);
            sMw[32 + lane]  = fmaxf(a01, 0.0f);
            sMw[64 + lane]  = fmaxf(a10, 0.0f);
            sMw[96 + lane]  = fmaxf(a11, 0.0f);
            sMw[128 + lane] = fmaxf(b00, 0.0f);
            sMw[160 + lane] = fmaxf(b01, 0.0f);
            sMw[192 + lane] = fmaxf(b10, 0.0f);
            sMw[224 + lane] = fmaxf(b11, 0.0f);
        }
        __syncwarp();

        // ---- fused LSTM: 4 rows share each weight load ----
        {
            const float4* wih = (const float4*)(sm + OFF_WIH);
            const float4* whh = (const float4*)(sm + OFF_WHH);
            float accA0[8], accA1[8], accB0[8], accB1[8];
#pragma unroll
            for (int c2 = 0; c2 < 4; c2++) {
                float blo = sm[OFF_BL + 4 * lane + c2];
                float bhi = sm[OFF_BL + 128 + 4 * lane + c2];
                accA0[c2] = blo; accA0[4 + c2] = bhi;
                accA1[c2] = blo; accA1[4 + c2] = bhi;
                accB0[c2] = blo; accB0[4 + c2] = bhi;
                accB1[c2] = blo; accB1[4 + c2] = bhi;
            }
#pragma unroll 2
            for (int k = 0; k < 64; k++) {
                float m0A = sMw[k], m1A = sMw[64 + k];
                float m0B = sMw[128 + k], m1B = sMw[192 + k];
                float h0A = sFA[k], h1A = sFA[64 + k];
                float h0B = sFB[k], h1B = sFB[64 + k];
                float4 wA = wih[(k << 6) + lane], wB = wih[(k << 6) + 32 + lane];
                float4 uA = whh[(k << 6) + lane], uB = whh[(k << 6) + 32 + lane];
                LSTM_STEP(accA0, m0A, h0A, wA, wB, uA, uB);
                LSTM_STEP(accA1, m1A, h1A, wA, wB, uA, uB);
                LSTM_STEP(accB0, m0B, h0B, wA, wB, uA, uB);
                LSTM_STEP(accB1, m1B, h1B, wA, wB, uA, uB);
            }
            lstm_epilogue(accA0, accA1, sA, dA, lane);
            lstm_epilogue(accB0, accB1, sB, dB, lane);
        }
        __syncwarp();
        if (lane == 0) {
            vdone[eA] = 1;
            if (eB0 >= 0) vdone[eB0] = 1;
        }
        __syncwarp();
    }

    grid_bar();  // classifier needs FINAL h

    // ---- classifier: logits[e] = [h[dst] || x[dst]] @ Wc + bc ----
    for (int i = tid; i < 192 * AA; i += NTHR) sm[OFF_WMT + i] = g_Wc[i];
    for (int i = tid; i < AA; i += NTHR) sm[OFF_WMT + 9600 + i] = g_bc[i];
    __syncthreads();
    const float* sWc = sm + OFF_WMT;
    const float* sBc = sm + OFF_WMT + 9600;

    for (int e = gw; e < EE; e += TOTWARP) {
        int d = ei[EE + e];
        __syncwarp();
        sFA[lane]      = g_h[(size_t)d * HH + lane];
        sFA[32 + lane] = g_h[(size_t)d * HH + 32 + lane];
        {
            const float4* xv = (const float4*)(x + (size_t)d * DF);
            ((float4*)(sFA + 64))[lane] = xv[lane];
        }
        __syncwarp();
        float r0 = sBc[lane];
        float r1 = (lane < AA - 32) ? sBc[32 + lane] : 0.0f;
        const float4* fvc = (const float4*)sFA;
#pragma unroll 4
        for (int q = 0; q < 48; ++q) {
            float4 f = fvc[q];
            int kb = 4 * q;
            r0 = fmaf(f.x, sWc[(kb + 0) * AA + lane], r0);
            r0 = fmaf(f.y, sWc[(kb + 1) * AA + lane], r0);
            r0 = fmaf(f.z, sWc[(kb + 2) * AA + lane], r0);
            r0 = fmaf(f.w, sWc[(kb + 3) * AA + lane], r0);
            r1 = fmaf(f.x, sWc[(kb + 0) * AA + 32 + lane], r1);
            r1 = fmaf(f.y, sWc[(kb + 1) * AA + 32 + lane], r1);
            r1 = fmaf(f.z, sWc[(kb + 2) * AA + 32 + lane], r1);
            r1 = fmaf(f.w, sWc[(kb + 3) * AA + 32 + lane], r1);
        }
        float* op = out + (size_t)e * AA;
        op[lane] = r0;
        if (lane < AA - 32) op[32 + lane] = r1;
    }
}

extern "C" void kernel_launch(void* const* d_in, const int* in_sizes, int n_in,
                              void* d_out, int out_size) {
    const float* x     = (const float*)d_in[0];
    const int*   ei    = (const int*)d_in[1];
    const float* eattr = (const float*)d_in[2];
    const float* etime = (const float*)d_in[3];
    const float* tw    = (const float*)d_in[4];
    const float* tb    = (const float*)d_in[5];
    const float* Wmsg  = (const float*)d_in[6];
    const float* bmsg  = (const float*)d_in[7];
    const float* Wih   = (const float*)d_in[8];
    const float* Whh   = (const float*)d_in[9];
    const float* blstm = (const float*)d_in[10];
    const float* Wemb  = (const float*)d_in[11];
    const float* bemb  = (const float*)d_in[12];
    const float* Wcls  = (const float*)d_in[13];
    const float* bcls  = (const float*)d_in[14];
    float* out = (float*)d_out;

    cudaFuncSetAttribute(k_pre, cudaFuncAttributeMaxDynamicSharedMemorySize, PRE_SMEM_BYTES);
    cudaFuncSetAttribute(k_sched, cudaFuncAttributeMaxDynamicSharedMemorySize, SCHED_SMEM_BYTES);
    cudaFuncSetAttribute(k_persist, cudaFuncAttributeMaxDynamicSharedMemorySize, SMEM_BYTES);

    k_pre<<<576, 512, PRE_SMEM_BYTES>>>(ei, Wemb, bemb, Wcls, bcls);
    k_sched<<<1, 1024, SCHED_SMEM_BYTES>>>();
    k_persist<<<NBLK, NTHR, SMEM_BYTES>>>(x, ei, eattr, etime, tw, tb, Wmsg, bmsg, Wih, Whh,
                                          blstm, out);
}

// round 6
// speedup vs baseline: 1.4762x; 1.4762x over previous
#include <cuda_runtime.h>
#include <cstdint>

#define NN 200000
#define EE 8192
#define HH 64
#define EAA 32
#define AA 50
#define DF 128

#define NBLK 148
#define NTHR 512
#define NWARP (NTHR / 32)
#define TOTWARP (NBLK * NWARP)

typedef unsigned long long u64;

// ---- persist shared memory layout (floats) ----
#define WMT_STRIDE 196
#define OFF_WMT 0
#define SZ_WMT (64 * WMT_STRIDE)            // 12544 (W_msg transposed, padded stride)
#define OFF_WIH (OFF_WMT + SZ_WMT)          // 12544
#define OFF_WHH (OFF_WIH + 16384)           // 28928
#define OFF_BM  (OFF_WHH + 16384)           // 45312
#define OFF_BL  (OFF_BM + 64)               // 45376
#define OFF_TW  (OFF_BL + 256)              // 45632
#define OFF_TB  (OFF_TW + 32)               // 45664
#define OFF_FEAT (OFF_TB + 32)              // 45696
#define OFF_M   (OFF_FEAT + NWARP * 192)    // 48768
#define SMEM_FLOATS (OFF_M + NWARP * 128)   // 50816
#define SMEM_BYTES (SMEM_FLOATS * 4)        // 203264

// ---- device scratch ----
__device__ float g_h[(size_t)NN * HH];
__device__ float g_c[(size_t)NN * HH];
__device__ int   g_done[EE];
__device__ int   g_prev_s[EE];
__device__ int   g_prev_d[EE];
__device__ int   g_head[NN];
__device__ int   g_next[2 * EE];
__device__ float g_Wc[192 * AA];
__device__ float g_bc[AA];
__device__ unsigned g_bar_cnt;
__device__ volatile unsigned g_bar_gen;

// ---- f32x2 packed math (Blackwell FFMA2; ptxas never auto-fuses this) ----
__device__ __forceinline__ u64 fma2(u64 a, u64 b, u64 c) {
    u64 d;
    asm("fma.rn.f32x2 %0, %1, %2, %3;" : "=l"(d) : "l"(a), "l"(b), "l"(c));
    return d;
}
__device__ __forceinline__ u64 pack2(float lo, float hi) {
    u64 r;
    asm("mov.b64 %0, {%1, %2};" : "=l"(r) : "f"(lo), "f"(hi));
    return r;
}
__device__ __forceinline__ float2 unpack2(u64 v) {
    float2 f;
    asm("mov.b64 {%0, %1}, %2;" : "=f"(f.x), "=f"(f.y) : "l"(v));
    return f;
}

__device__ __forceinline__ void grid_bar() {
    __syncthreads();
    if (threadIdx.x == 0) {
        __threadfence();
        unsigned gen = g_bar_gen;
        if (atomicAdd(&g_bar_cnt, 1u) == (unsigned)(gridDim.x - 1u)) {
            g_bar_cnt = 0u;
            __threadfence();
            g_bar_gen = gen + 1u;
        } else {
            while (g_bar_gen == gen) __nanosleep(128);
            __threadfence();
        }
    }
    __syncthreads();
}

__device__ __forceinline__ float sigf(float v) { return 1.0f / (1.0f + __expf(-v)); }
__device__ __forceinline__ float tanhf_(float v) {
    float e = __expf(2.0f * v);
    return 1.0f - 2.0f / (e + 1.0f);
}

// ---- init: node-chain heads, zero touched h/c, fuse W_emb@W_cls, reset flags ----
__global__ void __launch_bounds__(512) k_init(const int* __restrict__ ei,
                                              const float* __restrict__ Wemb,
                                              const float* __restrict__ bemb,
                                              const float* __restrict__ Wcls,
                                              const float* __restrict__ bcls) {
    int t = blockIdx.x * blockDim.x + threadIdx.x;  // 65536 threads
    if (t < 2 * EE) g_head[ei[t]] = -1;
    {   // 4 threads per endpoint zero h/c (dupes benign)
        int ep = t >> 2, part = t & 3;
        if (ep < 2 * EE) {
            int v = ei[ep];
            float4 z = make_float4(0.f, 0.f, 0.f, 0.f);
            float4* hp = (float4*)(g_h + (size_t)v * HH + part * 16);
            float4* cp = (float4*)(g_c + (size_t)v * HH + part * 16);
#pragma unroll
            for (int i = 0; i < 4; i++) { hp[i] = z; cp[i] = z; }
        }
    }
    if (t < EE) g_done[t] = 0;
    if (t < 192 * AA) {
        int k = t / AA, a = t - k * AA;
        float s = 0.0f;
        const float* wr = Wemb + k * HH;
#pragma unroll 8
        for (int j = 0; j < HH; j++) s = fmaf(wr[j], Wcls[j * AA + a], s);
        g_Wc[t] = s;
    }
    if (t < AA) {
        float s = bcls[t];
        for (int j = 0; j < HH; j++) s = fmaf(bemb[j], Wcls[j * AA + t], s);
        g_bc[t] = s;
    }
    if (t == 0) { g_bar_cnt = 0u; g_bar_gen = 0u; }
}

// ---- build per-node endpoint chains (unordered) ----
__global__ void __launch_bounds__(512) k_chain(const int* __restrict__ ei) {
    int t = blockIdx.x * blockDim.x + threadIdx.x;
    if (t < 2 * EE) g_next[t] = atomicExch(&g_head[ei[t]], t);
}

// ---- extract immediate predecessor per endpoint (chains are ~1 entry avg) ----
__global__ void __launch_bounds__(512) k_prevk(const int* __restrict__ ei) {
    int t = blockIdx.x * blockDim.x + threadIdx.x;
    if (t >= 2 * EE) return;
    int v = ei[t];
    int e = (t < EE) ? t : t - EE;
    int best = -1;
    for (int j = g_head[v]; j >= 0; j = g_next[j]) {
        int ev = (j < EE) ? j : j - EE;
        if (ev < e && ev > best) best = ev;
    }
    if (t < EE) g_prev_s[e] = best;
    else        g_prev_d[e] = best;
}

// ---- persistent: dataflow singles with f32x2 math ----
__global__ void __launch_bounds__(NTHR, 1) k_persist(
    const float* __restrict__ x, const int* __restrict__ ei, const float* __restrict__ eattr,
    const float* __restrict__ etime, const float* __restrict__ tw, const float* __restrict__ tb,
    const float* __restrict__ Wmsg, const float* __restrict__ bmsg,
    const float* __restrict__ Wih, const float* __restrict__ Whh,
    const float* __restrict__ blstm, float* __restrict__ out) {
    extern __shared__ float sm[];
    const int tid = threadIdx.x;
    const int lane = tid & 31;
    const int wid = tid >> 5;

    // stage weights (W_msg transposed, padded stride; conflict-free LDS.128)
    for (int i = tid; i < 192 * 64; i += NTHR) {
        int k = i >> 6, j = i & 63;
        sm[OFF_WMT + j * WMT_STRIDE + k] = Wmsg[i];
    }
    {
        float4* d1 = (float4*)(sm + OFF_WIH);
        float4* d2 = (float4*)(sm + OFF_WHH);
        const float4* s1 = (const float4*)Wih;
        const float4* s2 = (const float4*)Whh;
        for (int i = tid; i < 4096; i += NTHR) { d1[i] = s1[i]; d2[i] = s2[i]; }
    }
    for (int i = tid; i < 64; i += NTHR) sm[OFF_BM + i] = bmsg[i];
    for (int i = tid; i < 256; i += NTHR) sm[OFF_BL + i] = blstm[i];
    if (tid < 32) { sm[OFF_TW + tid] = tw[tid]; sm[OFF_TB + tid] = tb[tid]; }
    __syncthreads();

    const int gw = blockIdx.x * NWARP + wid;
    float* sF = sm + OFF_FEAT + wid * 192;
    float* sMw = sm + OFF_M + wid * 128;
    volatile int* vdone = (volatile int*)g_done;

    for (int e = gw; e < EE; e += TOTWARP) {
        int s = ei[e], d = ei[EE + e];
        int ps = g_prev_s[e], pd = g_prev_d[e];
        if (lane == 0) {
            int spins = 0;
            while ((ps >= 0 && vdone[ps] == 0) || (pd >= 0 && vdone[pd] == 0)) {
                __nanosleep(40);
                if (++spins > 20000000) break;  // fail visibly, never hang
            }
        }
        __syncwarp();
        __threadfence();  // acquire: order after flags; drop stale L1 h/c lines

        // ---- stage features: [0:64)=hs [64:128)=hd [128:160)=ea [160:192)=te ----
        {
            float t = etime[e];
            sF[lane]       = g_h[(size_t)s * HH + lane];
            sF[32 + lane]  = g_h[(size_t)s * HH + 32 + lane];
            sF[64 + lane]  = g_h[(size_t)d * HH + lane];
            sF[96 + lane]  = g_h[(size_t)d * HH + 32 + lane];
            sF[128 + lane] = eattr[(size_t)e * EAA + lane];
            sF[160 + lane] = cosf(fmaf(t, sm[OFF_TW + lane], sm[OFF_TB + lane]));
        }
        __syncwarp();

        // ---- message GEMV via f32x2: acc pairs over adjacent k ----
        {
            const ulonglong2* w0p = (const ulonglong2*)(sm + OFF_WMT + lane * WMT_STRIDE);
            const ulonglong2* w1p = (const ulonglong2*)(sm + OFF_WMT + (lane + 32) * WMT_STRIDE);
            const ulonglong2* fv = (const ulonglong2*)sF;
            u64 a00 = pack2(sm[OFF_BM + lane], 0.0f);
            u64 a01 = pack2(sm[OFF_BM + 32 + lane], 0.0f);
            u64 a10 = a00, a11 = a01;
#pragma unroll
            for (int q = 0; q < 16; q++) {  // k[0,64): row0 -> hd, row1 -> hs
                ulonglong2 w0 = w0p[q], w1 = w1p[q];
                ulonglong2 f0 = fv[16 + q], f1 = fv[q];
                a00 = fma2(f0.x, w0.x, a00); a00 = fma2(f0.y, w0.y, a00);
                a01 = fma2(f0.x, w1.x, a01); a01 = fma2(f0.y, w1.y, a01);
                a10 = fma2(f1.x, w0.x, a10); a10 = fma2(f1.y, w0.y, a10);
                a11 = fma2(f1.x, w1.x, a11); a11 = fma2(f1.y, w1.y, a11);
            }
#pragma unroll
            for (int q = 16; q < 32; q++) {  // k[64,128): row0 -> hs, row1 -> hd
                ulonglong2 w0 = w0p[q], w1 = w1p[q];
                ulonglong2 f0 = fv[q - 16], f1 = fv[q];
                a00 = fma2(f0.x, w0.x, a00); a00 = fma2(f0.y, w0.y, a00);
                a01 = fma2(f0.x, w1.x, a01); a01 = fma2(f0.y, w1.y, a01);
                a10 = fma2(f1.x, w0.x, a10); a10 = fma2(f1.y, w0.y, a10);
                a11 = fma2(f1.x, w1.x, a11); a11 = fma2(f1.y, w1.y, a11);
            }
#pragma unroll
            for (int q = 32; q < 48; q++) {  // k[128,192): shared ea/te
                ulonglong2 w0 = w0p[q], w1 = w1p[q];
                ulonglong2 f = fv[q];
                a00 = fma2(f.x, w0.x, a00); a00 = fma2(f.y, w0.y, a00);
                a01 = fma2(f.x, w1.x, a01); a01 = fma2(f.y, w1.y, a01);
                a10 = fma2(f.x, w0.x, a10); a10 = fma2(f.y, w0.y, a10);
                a11 = fma2(f.x, w1.x, a11); a11 = fma2(f.y, w1.y, a11);
            }
            float2 p0 = unpack2(a00), p1 = unpack2(a01), p2 = unpack2(a10), p3 = unpack2(a11);
            sMw[lane]      = fmaxf(p0.x + p0.y, 0.0f);
            sMw[32 + lane] = fmaxf(p1.x + p1.y, 0.0f);
            sMw[64 + lane] = fmaxf(p2.x + p2.y, 0.0f);
            sMw[96 + lane] = fmaxf(p3.x + p3.y, 0.0f);
        }
        __syncwarp();

        // ---- LSTM gates via f32x2: acc pairs over adjacent output cols ----
        // sMw layout: [0:64) = row0 message, [64:128) = row1 message
        float acc0[8], acc1[8];
        {
            const ulonglong2* wih2 = (const ulonglong2*)(sm + OFF_WIH);
            const ulonglong2* whh2 = (const ulonglong2*)(sm + OFF_WHH);
            ulonglong2 bl_lo = *(const ulonglong2*)(sm + OFF_BL + 4 * lane);
            ulonglong2 bl_hi = *(const ulonglong2*)(sm + OFF_BL + 128 + 4 * lane);
            u64 A[4] = {bl_lo.x, bl_lo.y, bl_hi.x, bl_hi.y};
            u64 B[4] = {bl_lo.x, bl_lo.y, bl_hi.x, bl_hi.y};
#pragma unroll 8
            for (int k = 0; k < 64; k++) {
                float m0 = sMw[k], m1 = sMw[64 + k];
                float h0 = sF[k], h1 = sF[64 + k];
                u64 m0p = pack2(m0, m0), m1p = pack2(m1, m1);
                u64 h0p = pack2(h0, h0), h1p = pack2(h1, h1);
                ulonglong2 wa = wih2[(k << 6) + lane], wb = wih2[(k << 6) + 32 + lane];
                ulonglong2 ua = whh2[(k << 6) + lane], ub = whh2[(k << 6) + 32 + lane];
                A[0] = fma2(m0p, wa.x, A[0]); A[1] = fma2(m0p, wa.y, A[1]);
                A[2] = fma2(m0p, wb.x, A[2]); A[3] = fma2(m0p, wb.y, A[3]);
                A[0] = fma2(h0p, ua.x, A[0]); A[1] = fma2(h0p, ua.y, A[1]);
                A[2] = fma2(h0p, ub.x, A[2]); A[3] = fma2(h0p, ub.y, A[3]);
                B[0] = fma2(m1p, wa.x, B[0]); B[1] = fma2(m1p, wa.y, B[1]);
                B[2] = fma2(m1p, wb.x, B[2]); B[3] = fma2(m1p, wb.y, B[3]);
                B[0] = fma2(h1p, ua.x, B[0]); B[1] = fma2(h1p, ua.y, B[1]);
                B[2] = fma2(h1p, ub.x, B[2]); B[3] = fma2(h1p, ub.y, B[3]);
            }
#pragma unroll
            for (int j = 0; j < 4; j++) {
                float2 pa = unpack2(A[j]), pb = unpack2(B[j]);
                acc0[2 * j] = pa.x; acc0[2 * j + 1] = pa.y;
                acc1[2 * j] = pb.x; acc1[2 * j + 1] = pb.y;
            }
        }

        // ---- epilogue: lanes 0..15 = i|g, lanes 16..31 = f|o ----
        {
            float f0g[4], o0g[4], f1g[4], o1g[4];
#pragma unroll
            for (int c2 = 0; c2 < 4; c2++) {
                f0g[c2] = __shfl_down_sync(0xffffffffu, acc0[c2], 16);
                o0g[c2] = __shfl_down_sync(0xffffffffu, acc0[4 + c2], 16);
                f1g[c2] = __shfl_down_sync(0xffffffffu, acc1[c2], 16);
                o1g[c2] = __shfl_down_sync(0xffffffffu, acc1[4 + c2], 16);
            }
            if (lane < 16) {
                float4 c0 = *(const float4*)(g_c + (size_t)s * HH + 4 * lane);
                float4 c1 = *(const float4*)(g_c + (size_t)d * HH + 4 * lane);
                float c0a[4] = {c0.x, c0.y, c0.z, c0.w};
                float c1a[4] = {c1.x, c1.y, c1.z, c1.w};
                float cn0[4], hn0[4], cn1[4], hn1[4];
#pragma unroll
                for (int c2 = 0; c2 < 4; c2++) {
                    cn0[c2] = sigf(f0g[c2]) * c0a[c2] + sigf(acc0[c2]) * tanhf_(acc0[4 + c2]);
                    hn0[c2] = sigf(o0g[c2]) * tanhf_(cn0[c2]);
                    cn1[c2] = sigf(f1g[c2]) * c1a[c2] + sigf(acc1[c2]) * tanhf_(acc1[4 + c2]);
                    hn1[c2] = sigf(o1g[c2]) * tanhf_(cn1[c2]);
                }
                if (s != d) {  // src==dst: dst (row 1) update wins, matching scatter
                    *(float4*)(g_h + (size_t)s * HH + 4 * lane) = make_float4(hn0[0], hn0[1], hn0[2], hn0[3]);
                    *(float4*)(g_c + (size_t)s * HH + 4 * lane) = make_float4(cn0[0], cn0[1], cn0[2], cn0[3]);
                }
                *(float4*)(g_h + (size_t)d * HH + 4 * lane) = make_float4(hn1[0], hn1[1], hn1[2], hn1[3]);
                *(float4*)(g_c + (size_t)d * HH + 4 * lane) = make_float4(cn1[0], cn1[1], cn1[2], cn1[3]);
                __threadfence();  // each writer publishes its own stores
            }
        }
        __syncwarp();
        if (lane == 0) vdone[e] = 1;
        __syncwarp();
    }

    grid_bar();  // classifier needs FINAL h

    // ---- classifier: logits[e] = [h[dst] || x[dst]] @ Wc + bc ----
    for (int i = tid; i < 192 * AA; i += NTHR) sm[OFF_WMT + i] = g_Wc[i];
    for (int i = tid; i < AA; i += NTHR) sm[OFF_WMT + 9600 + i] = g_bc[i];
    __syncthreads();
    const float* sWc = sm + OFF_WMT;
    const float* sBc = sm + OFF_WMT + 9600;

    for (int e = gw; e < EE; e += TOTWARP) {
        int d = ei[EE + e];
        __syncwarp();
        sF[lane]      = g_h[(size_t)d * HH + lane];
        sF[32 + lane] = g_h[(size_t)d * HH + 32 + lane];
        {
            const float4* xv = (const float4*)(x + (size_t)d * DF);
            ((float4*)(sF + 64))[lane] = xv[lane];
        }
        __syncwarp();
        float r0 = sBc[lane];
        float r1 = (lane < AA - 32) ? sBc[32 + lane] : 0.0f;
        const float4* fvc = (const float4*)sF;
#pragma unroll 4
        for (int q = 0; q < 48; ++q) {
            float4 f = fvc[q];
            int kb = 4 * q;
            r0 = fmaf(f.x, sWc[(kb + 0) * AA + lane], r0);
            r0 = fmaf(f.y, sWc[(kb + 1) * AA + lane], r0);
            r0 = fmaf(f.z, sWc[(kb + 2) * AA + lane], r0);
            r0 = fmaf(f.w, sWc[(kb + 3) * AA + lane], r0);
            r1 = fmaf(f.x, sWc[(kb + 0) * AA + 32 + lane], r1);
            r1 = fmaf(f.y, sWc[(kb + 1) * AA + 32 + lane], r1);
            r1 = fmaf(f.z, sWc[(kb + 2) * AA + 32 + lane], r1);
            r1 = fmaf(f.w, sWc[(kb + 3) * AA + 32 + lane], r1);
        }
        float* op = out + (size_t)e * AA;
        op[lane] = r0;
        if (lane < AA - 32) op[32 + lane] = r1;
    }
}

extern "C" void kernel_launch(void* const* d_in, const int* in_sizes, int n_in,
                              void* d_out, int out_size) {
    const float* x     = (const float*)d_in[0];
    const int*   ei    = (const int*)d_in[1];
    const float* eattr = (const float*)d_in[2];
    const float* etime = (const float*)d_in[3];
    const float* tw    = (const float*)d_in[4];
    const float* tb    = (const float*)d_in[5];
    const float* Wmsg  = (const float*)d_in[6];
    const float* bmsg  = (const float*)d_in[7];
    const float* Wih   = (const float*)d_in[8];
    const float* Whh   = (const float*)d_in[9];
    const float* blstm = (const float*)d_in[10];
    const float* Wemb  = (const float*)d_in[11];
    const float* bemb  = (const float*)d_in[12];
    const float* Wcls  = (const float*)d_in[13];
    const float* bcls  = (const float*)d_in[14];
    float* out = (float*)d_out;

    cudaFuncSetAttribute(k_persist, cudaFuncAttributeMaxDynamicSharedMemorySize, SMEM_BYTES);

    k_init<<<128, 512>>>(ei, Wemb, bemb, Wcls, bcls);
    k_chain<<<32, 512>>>(ei);
    k_prevk<<<32, 512>>>(ei);
    k_persist<<<NBLK, NTHR, SMEM_BYTES>>>(x, ei, eattr, etime, tw, tb, Wmsg, bmsg, Wih, Whh,
                                          blstm, out);
}